// round 2
// baseline (speedup 1.0000x reference)
#include <cuda_runtime.h>
#include <cstdint>

#define N_NODES  100000
#define N_EDGES  1000000
#define HID      64
#define EDGE_D   32
#define N_GRAPHS 256

// ---------------- scratch (static device globals; no allocation) -------------
__device__ float g_h[N_NODES * HID];       // node features after lin (per layer, reused)
__device__ float g_agg0[N_NODES * HID];    // layer0 aggregated output
__device__ float g_agg1[N_NODES * HID];    // layer1 aggregated output
__device__ float g_p[N_EDGES];             // exp(alpha) per edge
__device__ float g_ae1[N_EDGES];           // layer1 edge logits (precomputed in layer0 pass)
__device__ float g_sden[N_NODES];          // softmax denominators
__device__ float g_as[N_NODES];            // source attention logits
__device__ float g_ad[N_NODES];            // dest attention logits
__device__ float g_we0[EDGE_D];            // We0 @ att_edge0
__device__ float g_we1[EDGE_D];            // We1 @ att_edge1
__device__ float g_gsum[N_GRAPHS * HID];
__device__ float g_gcnt[N_GRAPHS];
__device__ int   g_src[N_EDGES];           // edge sources as int32
__device__ int   g_dst[N_EDGES];           // edge dests as int32
__device__ int   g_batch[N_NODES];         // node->graph as int32
__device__ int   g_is32;                   // 1 if input indices are int32

// vectorized global reduction (sm_90+): 2x fewer red ops than scalar atomicAdd
__device__ __forceinline__ void red_add_v2(float* addr, float x, float y) {
    asm volatile(
        "{ .reg .u64 a; cvta.to.global.u64 a, %0; red.global.add.v2.f32 [a], {%1, %2}; }"
        :: "l"(addr), "f"(x), "f"(y) : "memory");
}

// ---------------- dtype detection: int32 vs int64 edge_index ----------------
// Genuine int64 node ids < 2^31 have zero high words. Int32 data read as int64
// has the NEXT index in the high word (nonzero w.p. ~1-1e-5 per slot).
__global__ void detect_dtype_kernel(const void* __restrict__ ei_raw) {
    const unsigned int* w = (const unsigned int*)ei_raw;
    int t = threadIdx.x;           // 64 threads check 64 candidate int64 slots
    unsigned int hi = w[2 * t + 1];
    unsigned int any = __syncthreads_or(hi != 0u);
    if (t == 0) g_is32 = (any != 0u) ? 1 : 0;
}

__global__ void convert_edges_kernel(const void* __restrict__ ei_raw) {
    int e = blockIdx.x * blockDim.x + threadIdx.x;
    if (e >= N_EDGES) return;
    if (g_is32) {
        const int* p = (const int*)ei_raw;
        g_src[e] = p[e];
        g_dst[e] = p[N_EDGES + e];
    } else {
        const long long* p = (const long long*)ei_raw;
        g_src[e] = (int)p[e];
        g_dst[e] = (int)p[N_EDGES + e];
    }
}

__global__ void convert_batch_kernel(const void* __restrict__ b_raw) {
    int n = blockIdx.x * blockDim.x + threadIdx.x;
    if (n >= N_NODES) return;
    if (g_is32) g_batch[n] = ((const int*)b_raw)[n];
    else        g_batch[n] = (int)((const long long*)b_raw)[n];
}

// ---------------- tiny precompute: w_e = We @ att_e for both layers ----------
__global__ void prep_we_kernel(const float* __restrict__ We0, const float* __restrict__ ae0,
                               const float* __restrict__ We1, const float* __restrict__ ae1) {
    int t = threadIdx.x;
    if (t < EDGE_D) {
        float s = 0.f;
        #pragma unroll
        for (int j = 0; j < HID; j++) s += We0[t * HID + j] * ae0[j];
        g_we0[t] = s;
    } else if (t < 2 * EDGE_D) {
        int r = t - EDGE_D;
        float s = 0.f;
        #pragma unroll
        for (int j = 0; j < HID; j++) s += We1[r * HID + j] * ae1[j];
        g_we1[r] = s;
    }
}

// ---------------- node GEMM + attention dots ---------------------------------
// h = (xin + addb?) @ W ;  a_s = h . att_s ; a_d = h . att_d
// block = 256 threads, 4 nodes per iteration; W column register-resident.
__global__ void node_gemm_kernel(const float* __restrict__ xin,
                                 const float* __restrict__ addb,   // may be null
                                 const float* __restrict__ W,
                                 const float* __restrict__ atts,
                                 const float* __restrict__ attd,
                                 float* __restrict__ hout,
                                 float* __restrict__ as_out,
                                 float* __restrict__ ad_out) {
    __shared__ float Wsh[HID * HID];
    __shared__ float xsh[4 * HID];
    __shared__ float ssh[HID];
    __shared__ float dsh[HID];
    __shared__ float red_s[8];
    __shared__ float red_d[8];

    int tid  = threadIdx.x;
    int j    = tid & 63;
    int sub  = tid >> 6;
    int warp = tid >> 5;

    for (int i = tid; i < HID * HID; i += 256) Wsh[i] = W[i];
    if (tid < HID) { ssh[tid] = atts[tid]; dsh[tid] = attd[tid]; }
    __syncthreads();

    float wreg[HID];
    #pragma unroll
    for (int k = 0; k < HID; k++) wreg[k] = Wsh[k * HID + j];

    float bcol = (addb != nullptr) ? addb[j] : 0.f;

    for (int base = blockIdx.x * 4; base < N_NODES; base += gridDim.x * 4) {
        __syncthreads();
        xsh[tid] = xin[base * HID + tid] + bcol;
        __syncthreads();

        float acc = 0.f;
        const float* xr = &xsh[sub * HID];
        #pragma unroll
        for (int k = 0; k < HID; k++) acc += xr[k] * wreg[k];

        hout[base * HID + tid] = acc;

        float sv = acc * ssh[j];
        float dv = acc * dsh[j];
        #pragma unroll
        for (int off = 16; off > 0; off >>= 1) {
            sv += __shfl_down_sync(0xffffffffu, sv, off);
            dv += __shfl_down_sync(0xffffffffu, dv, off);
        }
        if ((tid & 31) == 0) { red_s[warp] = sv; red_d[warp] = dv; }
        __syncthreads();
        if (tid < 4) {
            as_out[base + tid] = red_s[2 * tid] + red_s[2 * tid + 1];
            ad_out[base + tid] = red_d[2 * tid] + red_d[2 * tid + 1];
        }
    }
}

// ---------------- edge pass 1, layer 0: logits for BOTH layers ---------------
__global__ void edge_alpha0_kernel(const float* __restrict__ ea) {
    __shared__ float sw0[EDGE_D];
    __shared__ float sw1[EDGE_D];
    int tid = threadIdx.x;
    if (tid < EDGE_D) sw0[tid] = g_we0[tid];
    else if (tid < 2 * EDGE_D) sw1[tid - EDGE_D] = g_we1[tid - EDGE_D];
    __syncthreads();

    int e = blockIdx.x * blockDim.x + threadIdx.x;
    if (e >= N_EDGES) return;

    int s = g_src[e];
    int d = g_dst[e];

    const float4* row = (const float4*)(ea + (size_t)e * EDGE_D);
    float ae0 = 0.f, ae1 = 0.f;
    #pragma unroll
    for (int i = 0; i < EDGE_D / 4; i++) {
        float4 v = __ldg(&row[i]);
        ae0 += v.x * sw0[4*i] + v.y * sw0[4*i+1] + v.z * sw0[4*i+2] + v.w * sw0[4*i+3];
        ae1 += v.x * sw1[4*i] + v.y * sw1[4*i+1] + v.z * sw1[4*i+2] + v.w * sw1[4*i+3];
    }
    float al = g_as[s] + g_ad[d] + ae0;
    al = (al > 0.f) ? al : 0.2f * al;        // leaky relu
    float p = __expf(al);                    // no max-subtraction: identical softmax
    g_p[e]   = p;
    g_ae1[e] = ae1;
    atomicAdd(&g_sden[d], p);
}

// ---------------- edge pass 1, layer 1 (uses cached a_e1) --------------------
__global__ void edge_alpha1_kernel() {
    int e = blockIdx.x * blockDim.x + threadIdx.x;
    if (e >= N_EDGES) return;
    int s = g_src[e];
    int d = g_dst[e];
    float al = g_as[s] + g_ad[d] + g_ae1[e];
    al = (al > 0.f) ? al : 0.2f * al;
    float p = __expf(al);
    g_p[e] = p;
    atomicAdd(&g_sden[d], p);
}

// ---------------- edge pass 2: weighted gather/scatter -----------------------
// warp per edge: lane l handles features [2l, 2l+1] as float2, vector red.add
__global__ void edge_scatter_kernel(const float* __restrict__ h,
                                    float* __restrict__ agg) {
    int gtid = blockIdx.x * blockDim.x + threadIdx.x;
    int e    = gtid >> 5;
    int lane = gtid & 31;
    if (e >= N_EDGES) return;

    int s = g_src[e];
    int d = g_dst[e];
    float w = g_p[e] / (g_sden[d] + 1e-16f);

    float2 hv = ((const float2*)h)[(size_t)s * 32 + lane];
    red_add_v2(&agg[(size_t)d * HID + 2 * lane], hv.x * w, hv.y * w);
}

// ---------------- pooling ----------------------------------------------------
// warp per node: final feature = (agg0 + b0) + (agg1 + b1)
__global__ void pool_kernel(const float* __restrict__ b0,
                            const float* __restrict__ b1) {
    int gtid = blockIdx.x * blockDim.x + threadIdx.x;
    int n    = gtid >> 5;
    int lane = gtid & 31;
    if (n >= N_NODES) return;

    int g = g_batch[n];
    float2 v0 = ((const float2*)g_agg0)[(size_t)n * 32 + lane];
    float2 v1 = ((const float2*)g_agg1)[(size_t)n * 32 + lane];
    float2 bb0 = ((const float2*)b0)[lane];
    float2 bb1 = ((const float2*)b1)[lane];
    red_add_v2(&g_gsum[g * HID + 2 * lane], v0.x + v1.x + bb0.x + bb1.x,
                                            v0.y + v1.y + bb0.y + bb1.y);
    if (lane == 0) atomicAdd(&g_gcnt[g], 1.0f);
}

__global__ void finalize_kernel(float* __restrict__ out) {
    int i = blockIdx.x * HID + threadIdx.x;   // 256 blocks x 64 threads
    int g = i >> 6;
    float c = g_gcnt[g];
    if (c < 1.f) c = 1.f;
    out[i] = g_gsum[i] / c;
}

// ---------------- launcher ---------------------------------------------------
extern "C" void kernel_launch(void* const* d_in, const int* in_sizes, int n_in,
                              void* d_out, int out_size) {
    const float* x     = (const float*)d_in[0];
    const void*  ei    = d_in[1];
    const float* ea    = (const float*)d_in[2];
    const void*  batch = d_in[3];
    const float* W0   = (const float*)d_in[4];
    const float* as0  = (const float*)d_in[5];
    const float* ad0  = (const float*)d_in[6];
    const float* We0  = (const float*)d_in[7];
    const float* ae0v = (const float*)d_in[8];
    const float* b0   = (const float*)d_in[9];
    const float* W1   = (const float*)d_in[10];
    const float* as1  = (const float*)d_in[11];
    const float* ad1  = (const float*)d_in[12];
    const float* We1  = (const float*)d_in[13];
    const float* ae1v = (const float*)d_in[14];
    const float* b1   = (const float*)d_in[15];
    float* out = (float*)d_out;

    void *p_sden, *p_agg0, *p_agg1, *p_gsum, *p_gcnt, *p_h, *p_as, *p_ad;
    cudaGetSymbolAddress(&p_sden, g_sden);
    cudaGetSymbolAddress(&p_agg0, g_agg0);
    cudaGetSymbolAddress(&p_agg1, g_agg1);
    cudaGetSymbolAddress(&p_gsum, g_gsum);
    cudaGetSymbolAddress(&p_gcnt, g_gcnt);
    cudaGetSymbolAddress(&p_h,    g_h);
    cudaGetSymbolAddress(&p_as,   g_as);
    cudaGetSymbolAddress(&p_ad,   g_ad);

    float* hbuf = (float*)p_h;
    float* asb  = (float*)p_as;
    float* adb  = (float*)p_ad;

    // zero accumulators
    cudaMemsetAsync(p_sden, 0, N_NODES * sizeof(float));
    cudaMemsetAsync(p_agg0, 0, (size_t)N_NODES * HID * sizeof(float));
    cudaMemsetAsync(p_agg1, 0, (size_t)N_NODES * HID * sizeof(float));
    cudaMemsetAsync(p_gsum, 0, N_GRAPHS * HID * sizeof(float));
    cudaMemsetAsync(p_gcnt, 0, N_GRAPHS * sizeof(float));

    // index dtype detection + conversion to int32 scratch
    detect_dtype_kernel<<<1, 64>>>(ei);
    convert_edges_kernel<<<(N_EDGES + 255) / 256, 256>>>(ei);
    convert_batch_kernel<<<(N_NODES + 255) / 256, 256>>>(batch);

    prep_we_kernel<<<1, 64>>>(We0, ae0v, We1, ae1v);

    // ---- layer 0 ----
    node_gemm_kernel<<<1184, 256>>>(x, nullptr, W0, as0, ad0, hbuf, asb, adb);
    edge_alpha0_kernel<<<(N_EDGES + 255) / 256, 256>>>(ea);
    edge_scatter_kernel<<<N_EDGES / 8, 256>>>(hbuf, (float*)p_agg0);

    // ---- layer 1 ----
    cudaMemsetAsync(p_sden, 0, N_NODES * sizeof(float));
    node_gemm_kernel<<<1184, 256>>>((const float*)p_agg0, b0, W1, as1, ad1, hbuf, asb, adb);
    edge_alpha1_kernel<<<(N_EDGES + 255) / 256, 256>>>();
    edge_scatter_kernel<<<N_EDGES / 8, 256>>>(hbuf, (float*)p_agg1);

    // ---- pool + finalize ----
    pool_kernel<<<N_NODES / 8, 256>>>(b0, b1);
    finalize_kernel<<<N_GRAPHS, HID>>>(out);
}

// round 3
// speedup vs baseline: 1.2165x; 1.2165x over previous
#include <cuda_runtime.h>
#include <cstdint>

#define N_NODES  100000
#define N_EDGES  1000000
#define HID      64
#define EDGE_D   32
#define N_GRAPHS 256

// ---------------- scratch (static device globals; no allocation) -------------
__device__ float g_h[N_NODES * HID];       // node features after lin (per layer, reused)
__device__ float g_agg0[N_NODES * HID];    // layer0 unnormalized aggregate
__device__ float g_agg1[N_NODES * HID];    // layer1 unnormalized aggregate
__device__ float g_ae1[N_EDGES];           // layer1 edge logits (precomputed in layer0 pass)
__device__ float g_den0[N_NODES];          // layer0 softmax denominators
__device__ float g_den1[N_NODES];          // layer1 softmax denominators
__device__ float g_as[N_NODES];            // source attention logits
__device__ float g_ad[N_NODES];            // dest attention logits
__device__ float g_we0[EDGE_D];            // We0 @ att_edge0
__device__ float g_we1[EDGE_D];            // We1 @ att_edge1
__device__ float g_gsum[N_GRAPHS * HID];
__device__ float g_gcnt[N_GRAPHS];
__device__ int   g_src[N_EDGES];
__device__ int   g_dst[N_EDGES];
__device__ int   g_batch[N_NODES];
__device__ int   g_is32;

// ---------------- vectorized global reductions (sm_90+) ----------------------
__device__ __forceinline__ void red_add_v4(float* addr, float x, float y, float z, float w) {
    asm volatile(
        "{ .reg .u64 a; cvta.to.global.u64 a, %0; red.global.add.v4.f32 [a], {%1,%2,%3,%4}; }"
        :: "l"(addr), "f"(x), "f"(y), "f"(z), "f"(w) : "memory");
}
__device__ __forceinline__ void red_add_f32(float* addr, float x) {
    asm volatile(
        "{ .reg .u64 a; cvta.to.global.u64 a, %0; red.global.add.f32 [a], %1; }"
        :: "l"(addr), "f"(x) : "memory");
}

// ---------------- dtype detection: int32 vs int64 edge_index -----------------
__global__ void detect_dtype_kernel(const void* __restrict__ ei_raw) {
    const unsigned int* w = (const unsigned int*)ei_raw;
    int t = threadIdx.x;
    unsigned int hi = w[2 * t + 1];
    unsigned int any = __syncthreads_or(hi != 0u);
    if (t == 0) g_is32 = (any != 0u) ? 1 : 0;
}

__global__ void convert_edges_kernel(const void* __restrict__ ei_raw) {
    int e = blockIdx.x * blockDim.x + threadIdx.x;
    if (e >= N_EDGES) return;
    if (g_is32) {
        const int* p = (const int*)ei_raw;
        g_src[e] = p[e];
        g_dst[e] = p[N_EDGES + e];
    } else {
        const long long* p = (const long long*)ei_raw;
        g_src[e] = (int)p[e];
        g_dst[e] = (int)p[N_EDGES + e];
    }
}

__global__ void convert_batch_kernel(const void* __restrict__ b_raw) {
    int n = blockIdx.x * blockDim.x + threadIdx.x;
    if (n >= N_NODES) return;
    if (g_is32) g_batch[n] = ((const int*)b_raw)[n];
    else        g_batch[n] = (int)((const long long*)b_raw)[n];
}

// ---------------- tiny precompute: w_e = We @ att_e for both layers ----------
__global__ void prep_we_kernel(const float* __restrict__ We0, const float* __restrict__ ae0,
                               const float* __restrict__ We1, const float* __restrict__ ae1) {
    int t = threadIdx.x;
    if (t < EDGE_D) {
        float s = 0.f;
        #pragma unroll
        for (int j = 0; j < HID; j++) s += We0[t * HID + j] * ae0[j];
        g_we0[t] = s;
    } else if (t < 2 * EDGE_D) {
        int r = t - EDGE_D;
        float s = 0.f;
        #pragma unroll
        for (int j = 0; j < HID; j++) s += We1[r * HID + j] * ae1[j];
        g_we1[r] = s;
    }
}

// ---------------- node GEMM + attention dots ---------------------------------
// h = (xin*rden? + addb?) @ W ;  a_s = h . att_s ; a_d = h . att_d
__global__ void node_gemm_kernel(const float* __restrict__ xin,
                                 const float* __restrict__ den,    // may be null
                                 const float* __restrict__ addb,   // may be null
                                 const float* __restrict__ W,
                                 const float* __restrict__ atts,
                                 const float* __restrict__ attd,
                                 float* __restrict__ hout,
                                 float* __restrict__ as_out,
                                 float* __restrict__ ad_out) {
    __shared__ float Wsh[HID * HID];
    __shared__ float xsh[4 * HID];
    __shared__ float ssh[HID];
    __shared__ float dsh[HID];
    __shared__ float red_s[8];
    __shared__ float red_d[8];

    int tid  = threadIdx.x;
    int j    = tid & 63;
    int sub  = tid >> 6;
    int warp = tid >> 5;

    for (int i = tid; i < HID * HID; i += 256) Wsh[i] = W[i];
    if (tid < HID) { ssh[tid] = atts[tid]; dsh[tid] = attd[tid]; }
    __syncthreads();

    float wreg[HID];
    #pragma unroll
    for (int k = 0; k < HID; k++) wreg[k] = Wsh[k * HID + j];

    float bcol = (addb != nullptr) ? addb[j] : 0.f;

    for (int base = blockIdx.x * 4; base < N_NODES; base += gridDim.x * 4) {
        __syncthreads();
        float scale = 1.f;
        if (den != nullptr) scale = 1.f / (den[base + sub] + 1e-16f);
        xsh[tid] = xin[base * HID + tid] * scale + bcol;
        __syncthreads();

        float acc = 0.f;
        const float* xr = &xsh[sub * HID];
        #pragma unroll
        for (int k = 0; k < HID; k++) acc += xr[k] * wreg[k];

        hout[base * HID + tid] = acc;

        float sv = acc * ssh[j];
        float dv = acc * dsh[j];
        #pragma unroll
        for (int off = 16; off > 0; off >>= 1) {
            sv += __shfl_down_sync(0xffffffffu, sv, off);
            dv += __shfl_down_sync(0xffffffffu, dv, off);
        }
        if ((tid & 31) == 0) { red_s[warp] = sv; red_d[warp] = dv; }
        __syncthreads();
        if (tid < 4) {
            as_out[base + tid] = red_s[2 * tid] + red_s[2 * tid + 1];
            ad_out[base + tid] = red_d[2 * tid] + red_d[2 * tid + 1];
        }
    }
}

// ---------------- fused edge pass, layer 0 -----------------------------------
// 16 lanes per edge. Computes a_e0 & a_e1 (caches a_e1), p=exp(leakyrelu),
// scatters p*h[src] via red.v4, accumulates denominator. No normalization here.
__global__ void edge_fused0_kernel(const float* __restrict__ ea,
                                   const float* __restrict__ h,
                                   float* __restrict__ agg) {
    __shared__ float sw0[EDGE_D];
    __shared__ float sw1[EDGE_D];
    int tid = threadIdx.x;
    if (tid < EDGE_D) sw0[tid] = g_we0[tid];
    else if (tid < 2 * EDGE_D) sw1[tid - EDGE_D] = g_we1[tid - EDGE_D];
    __syncthreads();

    int gt = blockIdx.x * blockDim.x + tid;
    int e  = gt >> 4;
    int l  = gt & 15;
    if (e >= N_EDGES) return;

    int s = g_src[e];
    int d = g_dst[e];

    float2 ev = ((const float2*)ea)[(size_t)e * 16 + l];
    float ae0 = ev.x * sw0[2*l] + ev.y * sw0[2*l+1];
    float ae1 = ev.x * sw1[2*l] + ev.y * sw1[2*l+1];
    #pragma unroll
    for (int off = 8; off > 0; off >>= 1) {
        ae0 += __shfl_xor_sync(0xffffffffu, ae0, off);
        ae1 += __shfl_xor_sync(0xffffffffu, ae1, off);
    }

    float al = g_as[s] + g_ad[d] + ae0;
    al = (al > 0.f) ? al : 0.2f * al;       // leaky relu
    float p = __expf(al);                   // no max-subtraction (softmax-invariant)

    if (l == 0) {
        g_ae1[e] = ae1;
        red_add_f32(&g_den0[d], p);
    }

    float4 hv = ((const float4*)h)[(size_t)s * 16 + l];
    red_add_v4(&agg[(size_t)d * HID + 4 * l], hv.x * p, hv.y * p, hv.z * p, hv.w * p);
}

// ---------------- fused edge pass, layer 1 (uses cached a_e1) ----------------
__global__ void edge_fused1_kernel(const float* __restrict__ h,
                                   float* __restrict__ agg) {
    int gt = blockIdx.x * blockDim.x + threadIdx.x;
    int e  = gt >> 4;
    int l  = gt & 15;
    if (e >= N_EDGES) return;

    int s = g_src[e];
    int d = g_dst[e];

    float al = g_as[s] + g_ad[d] + g_ae1[e];
    al = (al > 0.f) ? al : 0.2f * al;
    float p = __expf(al);

    if (l == 0) red_add_f32(&g_den1[d], p);

    float4 hv = ((const float4*)h)[(size_t)s * 16 + l];
    red_add_v4(&agg[(size_t)d * HID + 4 * l], hv.x * p, hv.y * p, hv.z * p, hv.w * p);
}

// ---------------- pooling ----------------------------------------------------
// 16 lanes per node: final feature = agg0/den0 + b0 + agg1/den1 + b1
__global__ void pool_kernel(const float* __restrict__ b0,
                            const float* __restrict__ b1) {
    int gt = blockIdx.x * blockDim.x + threadIdx.x;
    int n  = gt >> 4;
    int l  = gt & 15;
    if (n >= N_NODES) return;

    int g = g_batch[n];
    float r0 = 1.f / (g_den0[n] + 1e-16f);
    float r1 = 1.f / (g_den1[n] + 1e-16f);
    float4 v0 = ((const float4*)g_agg0)[(size_t)n * 16 + l];
    float4 v1 = ((const float4*)g_agg1)[(size_t)n * 16 + l];
    float4 bb0 = ((const float4*)b0)[l];
    float4 bb1 = ((const float4*)b1)[l];
    red_add_v4(&g_gsum[g * HID + 4 * l],
               v0.x * r0 + v1.x * r1 + bb0.x + bb1.x,
               v0.y * r0 + v1.y * r1 + bb0.y + bb1.y,
               v0.z * r0 + v1.z * r1 + bb0.z + bb1.z,
               v0.w * r0 + v1.w * r1 + bb0.w + bb1.w);
    if (l == 0) red_add_f32(&g_gcnt[g], 1.0f);
}

__global__ void finalize_kernel(float* __restrict__ out) {
    int i = blockIdx.x * HID + threadIdx.x;   // 256 blocks x 64 threads
    int g = i >> 6;
    float c = g_gcnt[g];
    if (c < 1.f) c = 1.f;
    out[i] = g_gsum[i] / c;
}

// ---------------- launcher ---------------------------------------------------
extern "C" void kernel_launch(void* const* d_in, const int* in_sizes, int n_in,
                              void* d_out, int out_size) {
    const float* x     = (const float*)d_in[0];
    const void*  ei    = d_in[1];
    const float* ea    = (const float*)d_in[2];
    const void*  batch = d_in[3];
    const float* W0   = (const float*)d_in[4];
    const float* as0  = (const float*)d_in[5];
    const float* ad0  = (const float*)d_in[6];
    const float* We0  = (const float*)d_in[7];
    const float* ae0v = (const float*)d_in[8];
    const float* b0   = (const float*)d_in[9];
    const float* W1   = (const float*)d_in[10];
    const float* as1  = (const float*)d_in[11];
    const float* ad1  = (const float*)d_in[12];
    const float* We1  = (const float*)d_in[13];
    const float* ae1v = (const float*)d_in[14];
    const float* b1   = (const float*)d_in[15];
    float* out = (float*)d_out;

    void *p_den0, *p_den1, *p_agg0, *p_agg1, *p_gsum, *p_gcnt, *p_h, *p_as, *p_ad;
    cudaGetSymbolAddress(&p_den0, g_den0);
    cudaGetSymbolAddress(&p_den1, g_den1);
    cudaGetSymbolAddress(&p_agg0, g_agg0);
    cudaGetSymbolAddress(&p_agg1, g_agg1);
    cudaGetSymbolAddress(&p_gsum, g_gsum);
    cudaGetSymbolAddress(&p_gcnt, g_gcnt);
    cudaGetSymbolAddress(&p_h,    g_h);
    cudaGetSymbolAddress(&p_as,   g_as);
    cudaGetSymbolAddress(&p_ad,   g_ad);

    float* hbuf = (float*)p_h;
    float* asb  = (float*)p_as;
    float* adb  = (float*)p_ad;

    // zero accumulators
    cudaMemsetAsync(p_den0, 0, N_NODES * sizeof(float));
    cudaMemsetAsync(p_den1, 0, N_NODES * sizeof(float));
    cudaMemsetAsync(p_agg0, 0, (size_t)N_NODES * HID * sizeof(float));
    cudaMemsetAsync(p_agg1, 0, (size_t)N_NODES * HID * sizeof(float));
    cudaMemsetAsync(p_gsum, 0, N_GRAPHS * HID * sizeof(float));
    cudaMemsetAsync(p_gcnt, 0, N_GRAPHS * sizeof(float));

    // index dtype detection + conversion to int32 scratch
    detect_dtype_kernel<<<1, 64>>>(ei);
    convert_edges_kernel<<<(N_EDGES + 255) / 256, 256>>>(ei);
    convert_batch_kernel<<<(N_NODES + 255) / 256, 256>>>(batch);

    prep_we_kernel<<<1, 64>>>(We0, ae0v, We1, ae1v);

    // ---- layer 0 ----
    node_gemm_kernel<<<1184, 256>>>(x, nullptr, nullptr, W0, as0, ad0, hbuf, asb, adb);
    edge_fused0_kernel<<<N_EDGES / 16, 256>>>(ea, hbuf, (float*)p_agg0);

    // ---- layer 1 (input = agg0/den0 + b0, fused into gemm load) ----
    node_gemm_kernel<<<1184, 256>>>((const float*)p_agg0, (const float*)p_den0, b0,
                                    W1, as1, ad1, hbuf, asb, adb);
    edge_fused1_kernel<<<N_EDGES / 16, 256>>>(hbuf, (float*)p_agg1);

    // ---- pool + finalize ----
    pool_kernel<<<N_NODES / 16, 256>>>(b0, b1);
    finalize_kernel<<<N_GRAPHS, HID>>>(out);
}

// round 5
// speedup vs baseline: 1.4705x; 1.2089x over previous
#include <cuda_runtime.h>
#include <cstdint>

#define N_NODES  100000
#define N_EDGES  1000000
#define HID      64
#define EDGE_D   32
#define N_GRAPHS 256
#define SCAN_BLK 1024
#define N_SCAN_BLKS ((N_NODES + SCAN_BLK - 1) / SCAN_BLK)   // 98

// ---------------- scratch (static device globals; no allocation) -------------
__device__ float g_h[N_NODES * HID];       // node features after lin (per layer)
__device__ float g_agg0[N_NODES * HID];    // layer0 NORMALIZED aggregate
__device__ float g_agg1[N_NODES * HID];    // layer1 NORMALIZED aggregate
__device__ float g_as[N_NODES];            // source attention logits
__device__ float g_ad[N_NODES];            // dest attention logits
__device__ float g_we0[EDGE_D];            // We0 @ att_edge0
__device__ float g_we1[EDGE_D];            // We1 @ att_edge1
__device__ float g_gsum[N_GRAPHS * HID];
__device__ float g_gcnt[N_GRAPHS];
__device__ int   g_src[N_EDGES];
__device__ int   g_dst[N_EDGES];
__device__ int   g_batch[N_NODES];
__device__ int   g_is32;
// CSR-by-dst structures
__device__ int    g_cnt[N_NODES];          // in-degree histogram
__device__ int    g_off[N_NODES + 1];      // CSR offsets
__device__ int    g_cur[N_NODES];          // scatter cursors
__device__ int    g_bsum[128];             // scan block sums
__device__ int    g_bexcl[128];            // scanned block sums
__device__ float4 g_edges[N_EDGES];        // packed {src_bits, ae0, ae1, pad}, dst-sorted

// ---------------- vectorized global reductions (sm_90+) ----------------------
__device__ __forceinline__ void red_add_v4(float* addr, float x, float y, float z, float w) {
    asm volatile(
        "{ .reg .u64 a; cvta.to.global.u64 a, %0; red.global.add.v4.f32 [a], {%1,%2,%3,%4}; }"
        :: "l"(addr), "f"(x), "f"(y), "f"(z), "f"(w) : "memory");
}
__device__ __forceinline__ void red_add_f32(float* addr, float x) {
    asm volatile(
        "{ .reg .u64 a; cvta.to.global.u64 a, %0; red.global.add.f32 [a], %1; }"
        :: "l"(addr), "f"(x) : "memory");
}

// ---------------- dtype detection: int32 vs int64 edge_index -----------------
__global__ void detect_dtype_kernel(const void* __restrict__ ei_raw) {
    const unsigned int* w = (const unsigned int*)ei_raw;
    int t = threadIdx.x;
    unsigned int hi = w[2 * t + 1];
    unsigned int any = __syncthreads_or(hi != 0u);
    if (t == 0) g_is32 = (any != 0u) ? 1 : 0;
}

// convert indices + build in-degree histogram
__global__ void convert_edges_kernel(const void* __restrict__ ei_raw) {
    int e = blockIdx.x * blockDim.x + threadIdx.x;
    if (e >= N_EDGES) return;
    int s, d;
    if (g_is32) {
        const int* p = (const int*)ei_raw;
        s = p[e]; d = p[N_EDGES + e];
    } else {
        const long long* p = (const long long*)ei_raw;
        s = (int)p[e]; d = (int)p[N_EDGES + e];
    }
    g_src[e] = s;
    g_dst[e] = d;
    atomicAdd(&g_cnt[d], 1);
}

__global__ void convert_batch_kernel(const void* __restrict__ b_raw) {
    int n = blockIdx.x * blockDim.x + threadIdx.x;
    if (n >= N_NODES) return;
    if (g_is32) g_batch[n] = ((const int*)b_raw)[n];
    else        g_batch[n] = (int)((const long long*)b_raw)[n];
}

// ---------------- 2-level exclusive scan of g_cnt -> g_off -------------------
__global__ void scan1_kernel() {
    __shared__ int sh[SCAN_BLK];
    int tid = threadIdx.x;
    int i = blockIdx.x * SCAN_BLK + tid;
    int v = (i < N_NODES) ? g_cnt[i] : 0;
    sh[tid] = v;
    __syncthreads();
    for (int ofs = 1; ofs < SCAN_BLK; ofs <<= 1) {
        int t = (tid >= ofs) ? sh[tid - ofs] : 0;
        __syncthreads();
        sh[tid] += t;
        __syncthreads();
    }
    if (i < N_NODES) g_off[i] = sh[tid] - v;       // exclusive within block
    if (tid == SCAN_BLK - 1) g_bsum[blockIdx.x] = sh[tid];
}

__global__ void scan2_kernel() {
    __shared__ int sh[128];
    int tid = threadIdx.x;
    int v = (tid < N_SCAN_BLKS) ? g_bsum[tid] : 0;
    sh[tid] = v;
    __syncthreads();
    for (int ofs = 1; ofs < 128; ofs <<= 1) {
        int t = (tid >= ofs) ? sh[tid - ofs] : 0;
        __syncthreads();
        sh[tid] += t;
        __syncthreads();
    }
    g_bexcl[tid] = sh[tid] - v;                    // exclusive
}

__global__ void scan3_kernel() {
    int i = blockIdx.x * SCAN_BLK + threadIdx.x;
    if (i < N_NODES) {
        int o = g_off[i] + g_bexcl[blockIdx.x];
        g_off[i] = o;
        g_cur[i] = o;
    }
    if (i == 0) g_off[N_NODES] = N_EDGES;
}

// ---------------- tiny precompute: w_e = We @ att_e for both layers ----------
__global__ void prep_we_kernel(const float* __restrict__ We0, const float* __restrict__ ae0,
                               const float* __restrict__ We1, const float* __restrict__ ae1) {
    int t = threadIdx.x;
    if (t < EDGE_D) {
        float s = 0.f;
        #pragma unroll
        for (int j = 0; j < HID; j++) s += We0[t * HID + j] * ae0[j];
        g_we0[t] = s;
    } else if (t < 2 * EDGE_D) {
        int r = t - EDGE_D;
        float s = 0.f;
        #pragma unroll
        for (int j = 0; j < HID; j++) s += We1[r * HID + j] * ae1[j];
        g_we1[r] = s;
    }
}

// ---------------- CSR build: bucket-scatter packed edge records --------------
// One thread per edge: computes a_e for BOTH layers from edge_attr (only read
// of ea in the whole pipeline), claims slot in dst bucket, stores 16B record.
__global__ void build_csr_kernel(const float* __restrict__ ea) {
    __shared__ float sw0[EDGE_D];
    __shared__ float sw1[EDGE_D];
    int tid = threadIdx.x;
    if (tid < EDGE_D) sw0[tid] = g_we0[tid];
    else if (tid < 2 * EDGE_D) sw1[tid - EDGE_D] = g_we1[tid - EDGE_D];
    __syncthreads();

    int e = blockIdx.x * blockDim.x + tid;
    if (e >= N_EDGES) return;

    const float4* row = (const float4*)(ea + (size_t)e * EDGE_D);
    float ae0 = 0.f, ae1 = 0.f;
    #pragma unroll
    for (int i = 0; i < EDGE_D / 4; i++) {
        float4 v = __ldg(&row[i]);
        ae0 += v.x * sw0[4*i] + v.y * sw0[4*i+1] + v.z * sw0[4*i+2] + v.w * sw0[4*i+3];
        ae1 += v.x * sw1[4*i] + v.y * sw1[4*i+1] + v.z * sw1[4*i+2] + v.w * sw1[4*i+3];
    }

    int d = g_dst[e];
    int pos = atomicAdd(&g_cur[d], 1);
    g_edges[pos] = make_float4(__int_as_float(g_src[e]), ae0, ae1, 0.f);
}

// ---------------- node GEMM + attention dots ---------------------------------
__global__ void node_gemm_kernel(const float* __restrict__ xin,
                                 const float* __restrict__ addb,   // may be null
                                 const float* __restrict__ W,
                                 const float* __restrict__ atts,
                                 const float* __restrict__ attd,
                                 float* __restrict__ hout,
                                 float* __restrict__ as_out,
                                 float* __restrict__ ad_out) {
    __shared__ float Wsh[HID * HID];
    __shared__ float xsh[4 * HID];
    __shared__ float ssh[HID];
    __shared__ float dsh[HID];
    __shared__ float red_s[8];
    __shared__ float red_d[8];

    int tid  = threadIdx.x;
    int j    = tid & 63;
    int sub  = tid >> 6;
    int warp = tid >> 5;

    for (int i = tid; i < HID * HID; i += 256) Wsh[i] = W[i];
    if (tid < HID) { ssh[tid] = atts[tid]; dsh[tid] = attd[tid]; }
    __syncthreads();

    float wreg[HID];
    #pragma unroll
    for (int k = 0; k < HID; k++) wreg[k] = Wsh[k * HID + j];

    float bcol = (addb != nullptr) ? addb[j] : 0.f;

    for (int base = blockIdx.x * 4; base < N_NODES; base += gridDim.x * 4) {
        __syncthreads();
        xsh[tid] = xin[base * HID + tid] + bcol;
        __syncthreads();

        float acc = 0.f;
        const float* xr = &xsh[sub * HID];
        #pragma unroll
        for (int k = 0; k < HID; k++) acc += xr[k] * wreg[k];

        hout[base * HID + tid] = acc;

        float sv = acc * ssh[j];
        float dv = acc * dsh[j];
        #pragma unroll
        for (int off = 16; off > 0; off >>= 1) {
            sv += __shfl_down_sync(0xffffffffu, sv, off);
            dv += __shfl_down_sync(0xffffffffu, dv, off);
        }
        if ((tid & 31) == 0) { red_s[warp] = sv; red_d[warp] = dv; }
        __syncthreads();
        if (tid < 4) {
            as_out[base + tid] = red_s[2 * tid] + red_s[2 * tid + 1];
            ad_out[base + tid] = red_d[2 * tid] + red_d[2 * tid + 1];
        }
    }
}

// ---------------- gather-only attention aggregate (atomic-free) --------------
// Warp per dst node; two half-warps split its incoming edges; lane l of a
// half-warp owns features [4l,4l+4). Writes NORMALIZED output directly.
template<int LAYER>
__global__ void agg_kernel(const float* __restrict__ h,
                           float* __restrict__ aggout) {
    int warp = (blockIdx.x * blockDim.x + threadIdx.x) >> 5;
    int lane = threadIdx.x & 31;
    int half = lane >> 4;
    int l    = lane & 15;
    int n    = warp;
    if (n >= N_NODES) return;

    int start = g_off[n];
    int end   = g_off[n + 1];
    float adn = g_ad[n];

    float4 acc = make_float4(0.f, 0.f, 0.f, 0.f);
    float dacc = 0.f;

    for (int i = start + half; i < end; i += 2) {
        float4 er = g_edges[i];                 // broadcast within half-warp
        int   src = __float_as_int(er.x);
        float ae  = (LAYER == 0) ? er.y : er.z;
        float al  = g_as[src] + adn + ae;
        al = (al > 0.f) ? al : 0.2f * al;       // leaky relu
        float p = __expf(al);                   // no max-sub (softmax invariant)
        float4 hv = ((const float4*)h)[(size_t)src * 16 + l];
        acc.x += p * hv.x; acc.y += p * hv.y;
        acc.z += p * hv.z; acc.w += p * hv.w;
        dacc  += p;
    }

    // combine the two half-warps
    acc.x += __shfl_xor_sync(0xffffffffu, acc.x, 16);
    acc.y += __shfl_xor_sync(0xffffffffu, acc.y, 16);
    acc.z += __shfl_xor_sync(0xffffffffu, acc.z, 16);
    acc.w += __shfl_xor_sync(0xffffffffu, acc.w, 16);
    dacc  += __shfl_xor_sync(0xffffffffu, dacc,  16);

    if (half == 0) {
        float r = 1.f / (dacc + 1e-16f);
        ((float4*)aggout)[(size_t)n * 16 + l] =
            make_float4(acc.x * r, acc.y * r, acc.z * r, acc.w * r);
    }
}

// ---------------- pooling ----------------------------------------------------
__global__ void pool_kernel(const float* __restrict__ b0,
                            const float* __restrict__ b1) {
    int gt = blockIdx.x * blockDim.x + threadIdx.x;
    int n  = gt >> 4;
    int l  = gt & 15;
    if (n >= N_NODES) return;

    int g = g_batch[n];
    float4 v0 = ((const float4*)g_agg0)[(size_t)n * 16 + l];
    float4 v1 = ((const float4*)g_agg1)[(size_t)n * 16 + l];
    float4 bb0 = ((const float4*)b0)[l];
    float4 bb1 = ((const float4*)b1)[l];
    red_add_v4(&g_gsum[g * HID + 4 * l],
               v0.x + v1.x + bb0.x + bb1.x,
               v0.y + v1.y + bb0.y + bb1.y,
               v0.z + v1.z + bb0.z + bb1.z,
               v0.w + v1.w + bb0.w + bb1.w);
    if (l == 0) red_add_f32(&g_gcnt[g], 1.0f);
}

__global__ void finalize_kernel(float* __restrict__ out) {
    int i = blockIdx.x * HID + threadIdx.x;   // 256 blocks x 64 threads
    int g = i >> 6;
    float c = g_gcnt[g];
    if (c < 1.f) c = 1.f;
    out[i] = g_gsum[i] / c;
}

// ---------------- launcher ---------------------------------------------------
extern "C" void kernel_launch(void* const* d_in, const int* in_sizes, int n_in,
                              void* d_out, int out_size) {
    const float* x     = (const float*)d_in[0];
    const void*  ei    = d_in[1];
    const float* ea    = (const float*)d_in[2];
    const void*  batch = d_in[3];
    const float* W0   = (const float*)d_in[4];
    const float* as0  = (const float*)d_in[5];
    const float* ad0  = (const float*)d_in[6];
    const float* We0  = (const float*)d_in[7];
    const float* ae0v = (const float*)d_in[8];
    const float* b0   = (const float*)d_in[9];
    const float* W1   = (const float*)d_in[10];
    const float* as1  = (const float*)d_in[11];
    const float* ad1  = (const float*)d_in[12];
    const float* We1  = (const float*)d_in[13];
    const float* ae1v = (const float*)d_in[14];
    const float* b1   = (const float*)d_in[15];
    float* out = (float*)d_out;

    void *p_cnt, *p_gsum, *p_gcnt, *p_h, *p_as, *p_ad, *p_agg0, *p_agg1;
    cudaGetSymbolAddress(&p_cnt,  g_cnt);
    cudaGetSymbolAddress(&p_gsum, g_gsum);
    cudaGetSymbolAddress(&p_gcnt, g_gcnt);
    cudaGetSymbolAddress(&p_h,    g_h);
    cudaGetSymbolAddress(&p_as,   g_as);
    cudaGetSymbolAddress(&p_ad,   g_ad);
    cudaGetSymbolAddress(&p_agg0, g_agg0);
    cudaGetSymbolAddress(&p_agg1, g_agg1);

    float* hbuf = (float*)p_h;
    float* asb  = (float*)p_as;
    float* adb  = (float*)p_ad;

    // zero accumulators (agg buffers written fully, no memset needed)
    cudaMemsetAsync(p_cnt,  0, N_NODES * sizeof(int));
    cudaMemsetAsync(p_gsum, 0, N_GRAPHS * HID * sizeof(float));
    cudaMemsetAsync(p_gcnt, 0, N_GRAPHS * sizeof(float));

    // index conversion + CSR build
    detect_dtype_kernel<<<1, 64>>>(ei);
    convert_edges_kernel<<<(N_EDGES + 255) / 256, 256>>>(ei);
    convert_batch_kernel<<<(N_NODES + 255) / 256, 256>>>(batch);
    scan1_kernel<<<N_SCAN_BLKS, SCAN_BLK>>>();
    scan2_kernel<<<1, 128>>>();
    scan3_kernel<<<N_SCAN_BLKS, SCAN_BLK>>>();
    prep_we_kernel<<<1, 64>>>(We0, ae0v, We1, ae1v);
    build_csr_kernel<<<(N_EDGES + 255) / 256, 256>>>(ea);

    // ---- layer 0 ----
    node_gemm_kernel<<<1184, 256>>>(x, nullptr, W0, as0, ad0, hbuf, asb, adb);
    agg_kernel<0><<<(N_NODES * 32 + 255) / 256, 256>>>(hbuf, (float*)p_agg0);

    // ---- layer 1 (input = normalized agg0 + b0, fused into gemm load) ----
    node_gemm_kernel<<<1184, 256>>>((const float*)p_agg0, b0, W1, as1, ad1, hbuf, asb, adb);
    agg_kernel<1><<<(N_NODES * 32 + 255) / 256, 256>>>(hbuf, (float*)p_agg1);

    // ---- pool + finalize ----
    pool_kernel<<<N_NODES / 16, 256>>>(b0, b1);
    finalize_kernel<<<N_GRAPHS, HID>>>(out);
}

// round 6
// speedup vs baseline: 1.5027x; 1.0219x over previous
#include <cuda_runtime.h>
#include <cstdint>

#define N_NODES  100000
#define N_EDGES  1000000
#define HID      64
#define EDGE_D   32
#define N_GRAPHS 256
#define SCAN_BLK 1024
#define N_SCAN_BLKS ((N_NODES + SCAN_BLK - 1) / SCAN_BLK)   // 98

// ---------------- scratch (static device globals; no allocation) -------------
__device__ float g_h[N_NODES * HID];       // node features after lin (per layer)
__device__ float g_agg0[N_NODES * HID];    // layer0 NORMALIZED aggregate
__device__ float g_as[N_NODES];            // source attention logits
__device__ float g_ad[N_NODES];            // dest attention logits
__device__ float g_we0[EDGE_D];            // We0 @ att_edge0
__device__ float g_we1[EDGE_D];            // We1 @ att_edge1
__device__ float g_gsum[N_GRAPHS * HID];
__device__ float g_gcnt[N_GRAPHS];
__device__ int   g_src[N_EDGES];
__device__ int   g_dst[N_EDGES];
__device__ int   g_batch[N_NODES];
__device__ int   g_is32;
// CSR-by-dst structures
__device__ int    g_cnt[N_NODES];          // in-degree histogram
__device__ int    g_off[N_NODES + 1];      // CSR offsets
__device__ int    g_cur[N_NODES];          // scatter cursors
__device__ int    g_bsum[128];             // scan block sums
__device__ int    g_bexcl[128];            // scanned block sums
__device__ float4 g_edges[N_EDGES];        // packed {src_bits, ae0, ae1, pad}, dst-sorted

// ---------------- vectorized global reductions (sm_90+) ----------------------
__device__ __forceinline__ void red_add_v4(float* addr, float x, float y, float z, float w) {
    asm volatile(
        "{ .reg .u64 a; cvta.to.global.u64 a, %0; red.global.add.v4.f32 [a], {%1,%2,%3,%4}; }"
        :: "l"(addr), "f"(x), "f"(y), "f"(z), "f"(w) : "memory");
}
__device__ __forceinline__ void red_add_f32(float* addr, float x) {
    asm volatile(
        "{ .reg .u64 a; cvta.to.global.u64 a, %0; red.global.add.f32 [a], %1; }"
        :: "l"(addr), "f"(x) : "memory");
}

// ---------------- dtype detection: int32 vs int64 edge_index -----------------
__global__ void detect_dtype_kernel(const void* __restrict__ ei_raw) {
    const unsigned int* w = (const unsigned int*)ei_raw;
    int t = threadIdx.x;
    unsigned int hi = w[2 * t + 1];
    unsigned int any = __syncthreads_or(hi != 0u);
    if (t == 0) g_is32 = (any != 0u) ? 1 : 0;
}

// convert indices + build in-degree histogram
__global__ void convert_edges_kernel(const void* __restrict__ ei_raw) {
    int e = blockIdx.x * blockDim.x + threadIdx.x;
    if (e >= N_EDGES) return;
    int s, d;
    if (g_is32) {
        const int* p = (const int*)ei_raw;
        s = p[e]; d = p[N_EDGES + e];
    } else {
        const long long* p = (const long long*)ei_raw;
        s = (int)p[e]; d = (int)p[N_EDGES + e];
    }
    g_src[e] = s;
    g_dst[e] = d;
    atomicAdd(&g_cnt[d], 1);
}

// convert batch indices + accumulate per-graph node counts
__global__ void convert_batch_kernel(const void* __restrict__ b_raw) {
    int n = blockIdx.x * blockDim.x + threadIdx.x;
    if (n >= N_NODES) return;
    int g;
    if (g_is32) g = ((const int*)b_raw)[n];
    else        g = (int)((const long long*)b_raw)[n];
    g_batch[n] = g;
    red_add_f32(&g_gcnt[g], 1.0f);
}

// ---------------- 2-level exclusive scan of g_cnt -> g_off -------------------
__global__ void scan1_kernel() {
    __shared__ int sh[SCAN_BLK];
    int tid = threadIdx.x;
    int i = blockIdx.x * SCAN_BLK + tid;
    int v = (i < N_NODES) ? g_cnt[i] : 0;
    sh[tid] = v;
    __syncthreads();
    for (int ofs = 1; ofs < SCAN_BLK; ofs <<= 1) {
        int t = (tid >= ofs) ? sh[tid - ofs] : 0;
        __syncthreads();
        sh[tid] += t;
        __syncthreads();
    }
    if (i < N_NODES) g_off[i] = sh[tid] - v;       // exclusive within block
    if (tid == SCAN_BLK - 1) g_bsum[blockIdx.x] = sh[tid];
}

__global__ void scan2_kernel() {
    __shared__ int sh[128];
    int tid = threadIdx.x;
    int v = (tid < N_SCAN_BLKS) ? g_bsum[tid] : 0;
    sh[tid] = v;
    __syncthreads();
    for (int ofs = 1; ofs < 128; ofs <<= 1) {
        int t = (tid >= ofs) ? sh[tid - ofs] : 0;
        __syncthreads();
        sh[tid] += t;
        __syncthreads();
    }
    g_bexcl[tid] = sh[tid] - v;                    // exclusive
}

__global__ void scan3_kernel() {
    int i = blockIdx.x * SCAN_BLK + threadIdx.x;
    if (i < N_NODES) {
        int o = g_off[i] + g_bexcl[blockIdx.x];
        g_off[i] = o;
        g_cur[i] = o;
    }
    if (i == 0) g_off[N_NODES] = N_EDGES;
}

// ---------------- tiny precompute: w_e = We @ att_e for both layers ----------
__global__ void prep_we_kernel(const float* __restrict__ We0, const float* __restrict__ ae0,
                               const float* __restrict__ We1, const float* __restrict__ ae1) {
    int t = threadIdx.x;
    if (t < EDGE_D) {
        float s = 0.f;
        #pragma unroll
        for (int j = 0; j < HID; j++) s += We0[t * HID + j] * ae0[j];
        g_we0[t] = s;
    } else if (t < 2 * EDGE_D) {
        int r = t - EDGE_D;
        float s = 0.f;
        #pragma unroll
        for (int j = 0; j < HID; j++) s += We1[r * HID + j] * ae1[j];
        g_we1[r] = s;
    }
}

// ---------------- CSR build: bucket-scatter packed edge records --------------
__global__ void build_csr_kernel(const float* __restrict__ ea) {
    __shared__ float sw0[EDGE_D];
    __shared__ float sw1[EDGE_D];
    int tid = threadIdx.x;
    if (tid < EDGE_D) sw0[tid] = g_we0[tid];
    else if (tid < 2 * EDGE_D) sw1[tid - EDGE_D] = g_we1[tid - EDGE_D];
    __syncthreads();

    int e = blockIdx.x * blockDim.x + tid;
    if (e >= N_EDGES) return;

    const float4* row = (const float4*)(ea + (size_t)e * EDGE_D);
    float ae0 = 0.f, ae1 = 0.f;
    #pragma unroll
    for (int i = 0; i < EDGE_D / 4; i++) {
        float4 v = __ldg(&row[i]);
        ae0 += v.x * sw0[4*i] + v.y * sw0[4*i+1] + v.z * sw0[4*i+2] + v.w * sw0[4*i+3];
        ae1 += v.x * sw1[4*i] + v.y * sw1[4*i+1] + v.z * sw1[4*i+2] + v.w * sw1[4*i+3];
    }

    int d = g_dst[e];
    int pos = atomicAdd(&g_cur[d], 1);
    g_edges[pos] = make_float4(__int_as_float(g_src[e]), ae0, ae1, 0.f);
}

// ---------------- node GEMM + attention dots ---------------------------------
__global__ void node_gemm_kernel(const float* __restrict__ xin,
                                 const float* __restrict__ addb,   // may be null
                                 const float* __restrict__ W,
                                 const float* __restrict__ atts,
                                 const float* __restrict__ attd,
                                 float* __restrict__ hout,
                                 float* __restrict__ as_out,
                                 float* __restrict__ ad_out) {
    __shared__ float Wsh[HID * HID];
    __shared__ float xsh[4 * HID];
    __shared__ float ssh[HID];
    __shared__ float dsh[HID];
    __shared__ float red_s[8];
    __shared__ float red_d[8];

    int tid  = threadIdx.x;
    int j    = tid & 63;
    int sub  = tid >> 6;
    int warp = tid >> 5;

    for (int i = tid; i < HID * HID; i += 256) Wsh[i] = W[i];
    if (tid < HID) { ssh[tid] = atts[tid]; dsh[tid] = attd[tid]; }
    __syncthreads();

    float wreg[HID];
    #pragma unroll
    for (int k = 0; k < HID; k++) wreg[k] = Wsh[k * HID + j];

    float bcol = (addb != nullptr) ? addb[j] : 0.f;

    for (int base = blockIdx.x * 4; base < N_NODES; base += gridDim.x * 4) {
        __syncthreads();
        xsh[tid] = xin[base * HID + tid] + bcol;
        __syncthreads();

        float acc = 0.f;
        const float* xr = &xsh[sub * HID];
        #pragma unroll
        for (int k = 0; k < HID; k++) acc += xr[k] * wreg[k];

        hout[base * HID + tid] = acc;

        float sv = acc * ssh[j];
        float dv = acc * dsh[j];
        #pragma unroll
        for (int off = 16; off > 0; off >>= 1) {
            sv += __shfl_down_sync(0xffffffffu, sv, off);
            dv += __shfl_down_sync(0xffffffffu, dv, off);
        }
        if ((tid & 31) == 0) { red_s[warp] = sv; red_d[warp] = dv; }
        __syncthreads();
        if (tid < 4) {
            as_out[base + tid] = red_s[2 * tid] + red_s[2 * tid + 1];
            ad_out[base + tid] = red_d[2 * tid] + red_d[2 * tid + 1];
        }
    }
}

// ---------------- gather-only attention aggregate (atomic-free) --------------
// Warp per dst node; two half-warps split edges; lane l owns features [4l,4l+4).
// Software-pipelined: next edge record prefetched while current h row gathers.
// LAYER==0: writes normalized agg to aggout.
// LAYER==1: fuses residual + biases + graph mean-pool accumulation (no aggout).
template<int LAYER>
__global__ void agg_kernel(const float* __restrict__ h,
                           float* __restrict__ aggout,
                           const float* __restrict__ b0,
                           const float* __restrict__ b1) {
    int warp = (blockIdx.x * blockDim.x + threadIdx.x) >> 5;
    int lane = threadIdx.x & 31;
    int half = lane >> 4;
    int l    = lane & 15;
    int n    = warp;
    if (n >= N_NODES) return;

    int start = g_off[n];
    int end   = g_off[n + 1];
    float adn = g_ad[n];

    float4 acc = make_float4(0.f, 0.f, 0.f, 0.f);
    float dacc = 0.f;

    int i = start + half;
    float4 er = make_float4(0.f, 0.f, 0.f, 0.f);
    if (i < end) er = g_edges[i];
    while (i < end) {
        int inext = i + 2;
        float4 er2 = make_float4(0.f, 0.f, 0.f, 0.f);
        if (inext < end) er2 = g_edges[inext];        // prefetch overlaps gathers below

        int   src = __float_as_int(er.x);
        float ae  = (LAYER == 0) ? er.y : er.z;
        float4 hv = ((const float4*)h)[(size_t)src * 16 + l];
        float al  = g_as[src] + adn + ae;
        al = (al > 0.f) ? al : 0.2f * al;             // leaky relu
        float p = __expf(al);                         // no max-sub (softmax invariant)
        acc.x += p * hv.x; acc.y += p * hv.y;
        acc.z += p * hv.z; acc.w += p * hv.w;
        dacc  += p;

        er = er2;
        i  = inext;
    }

    // combine the two half-warps
    acc.x += __shfl_xor_sync(0xffffffffu, acc.x, 16);
    acc.y += __shfl_xor_sync(0xffffffffu, acc.y, 16);
    acc.z += __shfl_xor_sync(0xffffffffu, acc.z, 16);
    acc.w += __shfl_xor_sync(0xffffffffu, acc.w, 16);
    dacc  += __shfl_xor_sync(0xffffffffu, dacc,  16);

    if (half == 0) {
        float r = 1.f / (dacc + 1e-16f);
        if (LAYER == 0) {
            ((float4*)aggout)[(size_t)n * 16 + l] =
                make_float4(acc.x * r, acc.y * r, acc.z * r, acc.w * r);
        } else {
            // fused residual + bias + graph mean-pool numerator
            float4 v0  = ((const float4*)g_agg0)[(size_t)n * 16 + l];
            float4 bb0 = ((const float4*)b0)[l];
            float4 bb1 = ((const float4*)b1)[l];
            int g = g_batch[n];
            red_add_v4(&g_gsum[g * HID + 4 * l],
                       acc.x * r + v0.x + bb0.x + bb1.x,
                       acc.y * r + v0.y + bb0.y + bb1.y,
                       acc.z * r + v0.z + bb0.z + bb1.z,
                       acc.w * r + v0.w + bb0.w + bb1.w);
        }
    }
}

__global__ void finalize_kernel(float* __restrict__ out) {
    int i = blockIdx.x * HID + threadIdx.x;   // 256 blocks x 64 threads
    int g = i >> 6;
    float c = g_gcnt[g];
    if (c < 1.f) c = 1.f;
    out[i] = g_gsum[i] / c;
}

// ---------------- launcher ---------------------------------------------------
extern "C" void kernel_launch(void* const* d_in, const int* in_sizes, int n_in,
                              void* d_out, int out_size) {
    const float* x     = (const float*)d_in[0];
    const void*  ei    = d_in[1];
    const float* ea    = (const float*)d_in[2];
    const void*  batch = d_in[3];
    const float* W0   = (const float*)d_in[4];
    const float* as0  = (const float*)d_in[5];
    const float* ad0  = (const float*)d_in[6];
    const float* We0  = (const float*)d_in[7];
    const float* ae0v = (const float*)d_in[8];
    const float* b0   = (const float*)d_in[9];
    const float* W1   = (const float*)d_in[10];
    const float* as1  = (const float*)d_in[11];
    const float* ad1  = (const float*)d_in[12];
    const float* We1  = (const float*)d_in[13];
    const float* ae1v = (const float*)d_in[14];
    const float* b1   = (const float*)d_in[15];
    float* out = (float*)d_out;

    void *p_cnt, *p_gsum, *p_gcnt, *p_h, *p_as, *p_ad, *p_agg0;
    cudaGetSymbolAddress(&p_cnt,  g_cnt);
    cudaGetSymbolAddress(&p_gsum, g_gsum);
    cudaGetSymbolAddress(&p_gcnt, g_gcnt);
    cudaGetSymbolAddress(&p_h,    g_h);
    cudaGetSymbolAddress(&p_as,   g_as);
    cudaGetSymbolAddress(&p_ad,   g_ad);
    cudaGetSymbolAddress(&p_agg0, g_agg0);

    float* hbuf = (float*)p_h;
    float* asb  = (float*)p_as;
    float* adb  = (float*)p_ad;

    // zero accumulators
    cudaMemsetAsync(p_cnt,  0, N_NODES * sizeof(int));
    cudaMemsetAsync(p_gsum, 0, N_GRAPHS * HID * sizeof(float));
    cudaMemsetAsync(p_gcnt, 0, N_GRAPHS * sizeof(float));

    // index conversion + CSR build
    detect_dtype_kernel<<<1, 64>>>(ei);
    convert_edges_kernel<<<(N_EDGES + 255) / 256, 256>>>(ei);
    convert_batch_kernel<<<(N_NODES + 255) / 256, 256>>>(batch);
    scan1_kernel<<<N_SCAN_BLKS, SCAN_BLK>>>();
    scan2_kernel<<<1, 128>>>();
    scan3_kernel<<<N_SCAN_BLKS, SCAN_BLK>>>();
    prep_we_kernel<<<1, 64>>>(We0, ae0v, We1, ae1v);
    build_csr_kernel<<<(N_EDGES + 255) / 256, 256>>>(ea);

    // ---- layer 0 ----
    node_gemm_kernel<<<1184, 256>>>(x, nullptr, W0, as0, ad0, hbuf, asb, adb);
    agg_kernel<0><<<(N_NODES * 32 + 255) / 256, 256>>>(hbuf, (float*)p_agg0, b0, b1);

    // ---- layer 1 (input = normalized agg0 + b0, fused into gemm load;
    //      agg pass fuses residual + pool) ----
    node_gemm_kernel<<<1184, 256>>>((const float*)p_agg0, b0, W1, as1, ad1, hbuf, asb, adb);
    agg_kernel<1><<<(N_NODES * 32 + 255) / 256, 256>>>(hbuf, nullptr, b0, b1);

    // ---- finalize (divide by per-graph counts) ----
    finalize_kernel<<<N_GRAPHS, HID>>>(out);
}